// round 17
// baseline (speedup 1.0000x reference)
#include <cuda_runtime.h>
#include <cuda_bf16.h>
#include <mma.h>
#include <math.h>

using namespace nvcuda;

#define BATCH 16384
#define FF    39
#define DD    16
#define DHD   32
#define VOCAB 10000

#define LOG2E 1.4426950408889634f

typedef unsigned long long ull;
typedef unsigned int uint;

// 41 MB intermediate: final attention output h in bf16, [BATCH][1248]
__device__ __nv_bfloat16 g_hb[(size_t)BATCH * 1248];

__device__ __forceinline__ ull pack2(float lo, float hi) {
  ull v; uint l = __float_as_uint(lo), h = __float_as_uint(hi);
  asm("mov.b64 %0, {%1, %2};" : "=l"(v) : "r"(l), "r"(h));
  return v;
}
__device__ __forceinline__ float frcp(float x) {
  float r; asm("rcp.approx.f32 %0, %1;" : "=f"(r) : "f"(x));
  return r;
}
__device__ __forceinline__ float fex2(float x) {
  float r; asm("ex2.approx.f32 %0, %1;" : "=f"(r) : "f"(x));
  return r;
}
__device__ __forceinline__ uint bfpack(float lo, float hi) {
  uint u; asm("cvt.rn.bf16x2.f32 %0, %1, %2;" : "=r"(u) : "f"(hi), "f"(lo));
  return u;
}

struct Params {
  const int* x; const float* emb;
  const float* wq0; const float* wk0; const float* wv0; const float* wr0;
  const float* wq1; const float* wk1; const float* wv1; const float* wr1;
  const float* wq2; const float* wk2; const float* wv2; const float* wr2;
  const float* w1; const float* b1; const float* w2; const float* b2;
  const float* w3; const float* b3; const float* w4; const float* b4;
  float* out;
};

// ===================== K1: tensor-core attention =====================
// 8 warps/CTA, one sample per warp. All matrices padded: fields 39->48,
// layer-0 din 16->32 (zero pads). e kept in bf16; pads are ZERO so the
// padded GEMMs are exact.
//
// per-warp byte layout (24576 B):
//  eb [48x32 bf16]      @0      (3072)   pad rows/cols zero, persistent
//  Tb [48x32 bf16]      @3072   (3072)
//  Vb [48x32 bf16]      @6144   (3072)
//  Pb [48x56 bf16]      @9216   (5376)
//  Ss [48x52 fp32]      @14592  (9984)  also fp32 scratch (ld 36) for converts
#define EB_B 0
#define TB_B 3072
#define VB_B 6144
#define PB_B 9216
#define SS_B 14592
#define PWB  24576
#define WSM_HALVES 9216     // 9 x 32x32 bf16 weight matrices
#define K1_SMEM (WSM_HALVES*2 + 8*PWB)   // 18432 + 196608 = 215040

typedef wmma::fragment<wmma::matrix_a, 16,16,16, __nv_bfloat16, wmma::row_major> fragA;
typedef wmma::fragment<wmma::matrix_b, 16,16,16, __nv_bfloat16, wmma::row_major> fragBr;
typedef wmma::fragment<wmma::matrix_b, 16,16,16, __nv_bfloat16, wmma::col_major> fragBc;
typedef wmma::fragment<wmma::accumulator, 16,16,16, float> fragC;

// C[3][2] = eb(48x32) @ W(32x32)
__device__ __forceinline__ void mm_eW(fragC cf[3][2],
    const __nv_bfloat16* eb, const __nv_bfloat16* W)
{
  #pragma unroll
  for (int mi = 0; mi < 3; mi++)
    #pragma unroll
    for (int nj = 0; nj < 2; nj++) wmma::fill_fragment(cf[mi][nj], 0.f);
  #pragma unroll
  for (int kk = 0; kk < 2; kk++) {
    fragA af[3];
    #pragma unroll
    for (int mi = 0; mi < 3; mi++)
      wmma::load_matrix_sync(af[mi], eb + mi*16*32 + kk*16, 32);
    #pragma unroll
    for (int nj = 0; nj < 2; nj++) {
      fragBr bf;
      wmma::load_matrix_sync(bf, W + kk*16*32 + nj*16, 32);
      #pragma unroll
      for (int mi = 0; mi < 3; mi++)
        wmma::mma_sync(cf[mi][nj], af[mi], bf, cf[mi][nj]);
    }
  }
}

// store C[3][2] to fp32 scratch (ld 36), convert 48x32 -> bf16 dst (ld 32)
__device__ __forceinline__ void cvt_store(fragC cf[3][2], float* scr,
                                          __nv_bfloat16* dst, int lane)
{
  #pragma unroll
  for (int mi = 0; mi < 3; mi++)
    #pragma unroll
    for (int nj = 0; nj < 2; nj++)
      wmma::store_matrix_sync(scr + mi*16*36 + nj*16, cf[mi][nj], 36,
                              wmma::mem_row_major);
  __syncwarp();
  uint* d32 = (uint*)dst;
  #pragma unroll
  for (int it = 0; it < 24; it++) {
    int i = lane + 32*it;          // 768 u32 = 48x32 bf16
    int r = i >> 4, cp = i & 15;
    d32[r*16 + cp] = bfpack(scr[r*36 + 2*cp], scr[r*36 + 2*cp + 1]);
  }
  __syncwarp();
}

__device__ void attn_layer_tc(char* wb, const __nv_bfloat16* Aw,
                              const __nv_bfloat16* Wv, const __nv_bfloat16* Wr,
                              int lane)
{
  __nv_bfloat16* eb = (__nv_bfloat16*)(wb + EB_B);
  __nv_bfloat16* Tb = (__nv_bfloat16*)(wb + TB_B);
  __nv_bfloat16* Vb = (__nv_bfloat16*)(wb + VB_B);
  __nv_bfloat16* Pb = (__nv_bfloat16*)(wb + PB_B);
  float* Ss  = (float*)(wb + SS_B);
  float* scr = Ss;

  // R = e @ Wr : held in fragments through the whole layer
  fragC rf[3][2];
  mm_eW(rf, eb, Wr);

  // T = e @ A -> Tb ; V = e @ Wv -> Vb (via fp32 scratch)
  {
    fragC cf[3][2];
    mm_eW(cf, eb, Aw);
    cvt_store(cf, scr, Tb, lane);
    mm_eW(cf, eb, Wv);
    cvt_store(cf, scr, Vb, lane);
  }

  // S = T @ e^T  (48x48, k=32), store fp32 ld 52
  {
    fragC sf[3][3];
    #pragma unroll
    for (int mi = 0; mi < 3; mi++)
      #pragma unroll
      for (int nj = 0; nj < 3; nj++) wmma::fill_fragment(sf[mi][nj], 0.f);
    #pragma unroll
    for (int kk = 0; kk < 2; kk++) {
      fragA af[3];
      #pragma unroll
      for (int mi = 0; mi < 3; mi++)
        wmma::load_matrix_sync(af[mi], Tb + mi*16*32 + kk*16, 32);
      #pragma unroll
      for (int nj = 0; nj < 3; nj++) {
        fragBc bc;   // e^T: col-major view of eb
        wmma::load_matrix_sync(bc, eb + nj*16*32 + kk*16, 32);
        #pragma unroll
        for (int mi = 0; mi < 3; mi++)
          wmma::mma_sync(sf[mi][nj], af[mi], bc, sf[mi][nj]);
      }
    }
    #pragma unroll
    for (int mi = 0; mi < 3; mi++)
      #pragma unroll
      for (int nj = 0; nj < 3; nj++)
        wmma::store_matrix_sync(Ss + mi*16*52 + nj*16, sf[mi][nj], 52,
                                wmma::mem_row_major);
  }
  __syncwarp();

  // softmax rows 0..38 (scores tiny; A pre-scaled by log2e so p = 2^s).
  // S cols 39..47 are exactly 0 (zero e-pads) but are EXCLUDED from the sum
  // and zeroed in P.
  {
    const bool has2 = (lane < 7);
    #pragma unroll 2
    for (int f = 0; f < FF; f++) {
      float s1 = Ss[f*52 + lane];
      float s2 = has2 ? Ss[f*52 + 32 + lane] : 0.f;
      float p1 = fex2(s1);
      float p2 = has2 ? fex2(s2) : 0.f;
      float sum = p1 + p2;
      #pragma unroll
      for (int o = 16; o; o >>= 1) sum += __shfl_xor_sync(0xffffffffu, sum, o);
      float inv = frcp(sum);
      Pb[f*56 + lane] = __float2bfloat16(p1 * inv);
      if (lane < 16)   // cols 32..47: valid for lanes<7, zero pads for 7..15
        Pb[f*56 + 32 + lane] = has2 ? __float2bfloat16(p2 * inv)
                                    : __float2bfloat16(0.f);
    }
  }
  __syncwarp();

  // O = P @ V + R (accumulate into rf), relu, -> eb rows 0..38
  {
    #pragma unroll
    for (int kk = 0; kk < 3; kk++) {
      fragA af[3];
      #pragma unroll
      for (int mi = 0; mi < 3; mi++)
        wmma::load_matrix_sync(af[mi], Pb + mi*16*56 + kk*16, 56);
      #pragma unroll
      for (int nj = 0; nj < 2; nj++) {
        fragBr bf;
        wmma::load_matrix_sync(bf, Vb + kk*16*32 + nj*16, 32);
        #pragma unroll
        for (int mi = 0; mi < 3; mi++)
          wmma::mma_sync(rf[mi][nj], af[mi], bf, rf[mi][nj]);
      }
    }
    #pragma unroll
    for (int mi = 0; mi < 3; mi++)
      #pragma unroll
      for (int nj = 0; nj < 2; nj++) {
        #pragma unroll
        for (int e = 0; e < rf[mi][nj].num_elements; e++)
          rf[mi][nj].x[e] = fmaxf(rf[mi][nj].x[e], 0.f);
        wmma::store_matrix_sync(scr + mi*16*36 + nj*16, rf[mi][nj], 36,
                                wmma::mem_row_major);
      }
  }
  __syncwarp();
  // convert rows 0..38 only (pad rows of eb stay zero)
  {
    uint* d32 = (uint*)eb;
    #pragma unroll
    for (int it = 0; it < 20; it++) {
      int i = lane + 32*it;            // 624 u32 = 39x32 bf16
      if (i < 624) {
        int r = i >> 4, cp = i & 15;
        d32[r*16 + cp] = bfpack(scr[r*36 + 2*cp], scr[r*36 + 2*cp + 1]);
      }
    }
  }
  __syncwarp();
}

__global__ void __launch_bounds__(256, 1) attn_kernel(Params p)
{
  extern __shared__ char smc[];
  __nv_bfloat16* wsm = (__nv_bfloat16*)smc;   // 9 x [32x32] weight mats
  const int tid  = threadIdx.x;
  const int warp = tid >> 5;
  const int lane = tid & 31;
  const int samp = blockIdx.x * 8 + warp;

  // ---- weight prep: zero, then A_l = LOG2E*Wq Wk^T + padded Wv/Wr ----
  for (int i = tid; i < WSM_HALVES/2; i += 256) ((uint*)wsm)[i] = 0;
  __syncthreads();
  // A matrices: A0 16x16 (mat 0), A1 32x32 (mat 1), A2 32x32 (mat 2)
  for (int idx = tid; idx < 2304; idx += 256) {
    int a, b; const float *wq_, *wk_; int mat;
    if (idx < 1024)      { a = idx >> 5;          b = idx & 31; wq_ = p.wq1; wk_ = p.wk1; mat = 1; }
    else if (idx < 2048) { a = (idx-1024) >> 5;   b = idx & 31; wq_ = p.wq2; wk_ = p.wk2; mat = 2; }
    else                 { int t = idx-2048; a = t >> 4; b = t & 15; wq_ = p.wq0; wk_ = p.wk0; mat = 0; }
    const float4* qa = (const float4*)(wq_ + a*DHD);
    const float4* kb = (const float4*)(wk_ + b*DHD);
    float s = 0.f;
    #pragma unroll
    for (int i4 = 0; i4 < 8; i4++) {
      float4 qv = qa[i4], kv = kb[i4];
      s += qv.x*kv.x + qv.y*kv.y + qv.z*kv.z + qv.w*kv.w;
    }
    wsm[mat*1024 + a*32 + b] = __float2bfloat16(s * LOG2E);
  }
  // Wv (mats 3,4,5) and Wr (mats 6,7,8); layer0 rows 16..31 remain zero
  for (int i = tid; i < 5120; i += 256) {
    int mat; const float* src; int j;
    if (i < 512)        { mat = 3; src = p.wv0; j = i; }
    else if (i < 1536)  { mat = 4; src = p.wv1; j = i - 512; }
    else if (i < 2560)  { mat = 5; src = p.wv2; j = i - 1536; }
    else if (i < 3072)  { mat = 6; src = p.wr0; j = i - 2560; }
    else if (i < 4096)  { mat = 7; src = p.wr1; j = i - 3072; }
    else                { mat = 8; src = p.wr2; j = i - 4096; }
    wsm[mat*1024 + j] = __float2bfloat16(src[j]);
  }

  char* wb = smc + WSM_HALVES*2 + warp * PWB;
  __nv_bfloat16* eb = (__nv_bfloat16*)(wb + EB_B);

  // zero eb (incl. pads), then gather embeddings into cols 0..15 (layer0 din)
  for (int i = lane; i < 768; i += 32) ((uint*)eb)[i] = 0;
  __syncwarp();
  {
    const int* xr = p.x + samp * FF;
    for (int i = lane; i < FF * DD; i += 32) {
      int f = i >> 4, d = i & 15;
      int row = xr[f] + f * VOCAB;
      eb[f*32 + d] = __float2bfloat16(p.emb[row * DD + d]);
    }
  }
  __syncthreads();   // weights visible

  attn_layer_tc(wb, wsm + 0*1024, wsm + 3*1024, wsm + 6*1024, lane);
  attn_layer_tc(wb, wsm + 1*1024, wsm + 4*1024, wsm + 7*1024, lane);
  attn_layer_tc(wb, wsm + 2*1024, wsm + 5*1024, wsm + 8*1024, lane);

  // write h (rows 0..38 of eb) to g_hb, coalesced u32
  {
    const uint* s32 = (const uint*)eb;
    uint* d32 = (uint*)(g_hb + (size_t)samp * 1248);
    #pragma unroll
    for (int it = 0; it < 20; it++) {
      int i = lane + 32*it;
      if (i < 624) d32[i] = s32[i];
    }
  }
}

// ============ K2: wmma bf16 MLP1 GEMM + fused MLP2-4 tail ============

#define MT 64
#define A_LD 24
#define B_LD 136
#define HS_LD 132

__global__ void __launch_bounds__(256) mlp_kernel(Params p)
{
  extern __shared__ char s2c[];
  __nv_bfloat16* As[2] = { (__nv_bfloat16*)s2c,
                           (__nv_bfloat16*)s2c + MT*A_LD };
  __nv_bfloat16* Bs[2] = { (__nv_bfloat16*)s2c + 2*MT*A_LD,
                           (__nv_bfloat16*)s2c + 2*MT*A_LD + 16*B_LD };
  float* Hs   = (float*)s2c;
  float* wscr = (float*)s2c + MT*HS_LD;

  const int tid  = threadIdx.x;
  const int warp = tid >> 5;
  const int lane = tid & 31;
  const int m0   = blockIdx.x * MT;

  const int ar = tid >> 2;
  const int ak = (tid & 3) * 4;
  const int bk = tid >> 4;
  const int bn = (tid & 15) * 8;

  const int wm = (warp & 3) * 16;
  const int wn = (warp >> 2) * 64;

  wmma::fragment<wmma::accumulator, 16, 16, 16, float> cf[4];
  #pragma unroll
  for (int j = 0; j < 4; j++) wmma::fill_fragment(cf[j], 0.f);

  auto stage = [&](int t, int b) {
    *(ull*)&As[b][ar*A_LD + ak] =
        *(const ull*)&g_hb[(size_t)(m0 + ar)*1248 + t*16 + ak];
    const float* ws = p.w1 + (t*16 + bk)*128 + bn;
    float4 w0 = *(const float4*)ws, w1v = *(const float4*)(ws + 4);
    __nv_bfloat16 tmp[8] = {
      __float2bfloat16(w0.x),  __float2bfloat16(w0.y),
      __float2bfloat16(w0.z),  __float2bfloat16(w0.w),
      __float2bfloat16(w1v.x), __float2bfloat16(w1v.y),
      __float2bfloat16(w1v.z), __float2bfloat16(w1v.w) };
    *(uint4*)&Bs[b][bk*B_LD + bn] = *(const uint4*)tmp;
  };

  stage(0, 0);
  __syncthreads();

  #pragma unroll 1
  for (int t = 0; t < 78; t++) {
    if (t < 77) stage(t + 1, (t + 1) & 1);
    const __nv_bfloat16* Ac = As[t & 1];
    const __nv_bfloat16* Bc = Bs[t & 1];
    wmma::fragment<wmma::matrix_a, 16, 16, 16, __nv_bfloat16, wmma::row_major> af;
    wmma::load_matrix_sync(af, Ac + wm*A_LD, A_LD);
    #pragma unroll
    for (int j = 0; j < 4; j++) {
      wmma::fragment<wmma::matrix_b, 16, 16, 16, __nv_bfloat16, wmma::row_major> bf;
      wmma::load_matrix_sync(bf, Bc + wn + j*16, B_LD);
      wmma::mma_sync(cf[j], af, bf, cf[j]);
    }
    __syncthreads();
  }

  #pragma unroll
  for (int j = 0; j < 4; j++)
    wmma::store_matrix_sync(Hs + wm*HS_LD + wn + j*16, cf[j], HS_LD,
                            wmma::mem_row_major);
  __syncthreads();
  {
    const int hr = tid >> 2;
    const int hc = (tid & 3) * 32;
    #pragma unroll
    for (int j = 0; j < 32; j++) {
      float v = Hs[hr*HS_LD + hc + j] + p.b1[hc + j];
      Hs[hr*HS_LD + hc + j] = fmaxf(v, 0.f);
    }
  }
  __syncthreads();

  float* mB = wscr + warp * 68;
  #pragma unroll 1
  for (int sl = warp; sl < MT; sl += 8) {
    const float* hrow = Hs + sl*HS_LD;
    float c0 = p.b2[lane], c1 = p.b2[lane + 32];
    #pragma unroll
    for (int k = 0; k < 128; k += 4) {
      float4 hv = *(const float4*)(hrow + k);
      c0 += hv.x*p.w2[(k+0)*64+lane]    + hv.y*p.w2[(k+1)*64+lane]
          + hv.z*p.w2[(k+2)*64+lane]    + hv.w*p.w2[(k+3)*64+lane];
      c1 += hv.x*p.w2[(k+0)*64+lane+32] + hv.y*p.w2[(k+1)*64+lane+32]
          + hv.z*p.w2[(k+2)*64+lane+32] + hv.w*p.w2[(k+3)*64+lane+32];
    }
    mB[lane]      = fmaxf(c0, 0.f);
    mB[lane + 32] = fmaxf(c1, 0.f);
    __syncwarp();

    float d0 = p.b3[lane];
    #pragma unroll
    for (int k = 0; k < 64; k += 4) {
      float4 hv = *(const float4*)(mB + k);
      d0 += hv.x*p.w3[(k+0)*32+lane] + hv.y*p.w3[(k+1)*32+lane]
          + hv.z*p.w3[(k+2)*32+lane] + hv.w*p.w3[(k+3)*32+lane];
    }
    float h3v = fmaxf(d0, 0.f);

    float part = h3v * p.w4[lane];
    #pragma unroll
    for (int off = 16; off; off >>= 1) part += __shfl_xor_sync(0xffffffffu, part, off);
    if (lane == 0) {
      float z = part + p.b4[0];
      p.out[m0 + sl] = 1.0f / (1.0f + __expf(-z));
    }
    __syncwarp();
  }
}

extern "C" void kernel_launch(void* const* d_in, const int* in_sizes, int n_in,
                              void* d_out, int out_size)
{
  Params p;
  p.x   = (const int*)  d_in[0];
  p.emb = (const float*)d_in[1];
  p.wq0 = (const float*)d_in[2];  p.wk0 = (const float*)d_in[3];
  p.wv0 = (const float*)d_in[4];  p.wr0 = (const float*)d_in[5];
  p.wq1 = (const float*)d_in[6];  p.wk1 = (const float*)d_in[7];
  p.wv1 = (const float*)d_in[8];  p.wr1 = (const float*)d_in[9];
  p.wq2 = (const float*)d_in[10]; p.wk2 = (const float*)d_in[11];
  p.wv2 = (const float*)d_in[12]; p.wr2 = (const float*)d_in[13];
  p.w1  = (const float*)d_in[14]; p.b1  = (const float*)d_in[15];
  p.w2  = (const float*)d_in[16]; p.b2  = (const float*)d_in[17];
  p.w3  = (const float*)d_in[18]; p.b3  = (const float*)d_in[19];
  p.w4  = (const float*)d_in[20]; p.b4  = (const float*)d_in[21];
  p.out = (float*)d_out;

  const int smem2 = (MT*HS_LD + 8*68) * (int)sizeof(float);   // 35,968 B
  cudaFuncSetAttribute(attn_kernel,
                       cudaFuncAttributeMaxDynamicSharedMemorySize, K1_SMEM);
  cudaFuncSetAttribute(mlp_kernel,
                       cudaFuncAttributeMaxDynamicSharedMemorySize, smem2);

  attn_kernel<<<BATCH / 8, 256, K1_SMEM>>>(p);
  mlp_kernel<<<BATCH / MT, 256, smem2>>>(p);
}